// round 1
// baseline (speedup 1.0000x reference)
#include <cuda_runtime.h>
#include <cstdint>

// ---------------------------------------------------------------------------
// Problem constants
// ---------------------------------------------------------------------------
// B=256, F=512, T=81, WIN=1022, HOP=400, SEG=1000, OVL=50, TO_HOP=100
// SIG_LEN=33022, _t=30, KEPT_LEN=30000, OUT_LEN=28550, NF=69
#define NB      256
#define NT      81
#define WIN     1022
#define NF      69
#define M1      (NB*NT)      // 20736  rows of GEMM1 (b,t)
#define M2      (NB*NF)      // 17664  rows of GEMM2 (b,f)
#define OUTJ    28550
#define OSTRIDE 28552        // padded (multiple of 4) row stride of out_sig
#define XBSTR   82944        // 512*81*2  batch stride of x
#define XKSTR   162          // 81*2      k stride of x
#define OBSTR   70656        // 512*69*2  batch stride of output
#define OKSTR   138          // 69*2      k stride of output

// ---------------------------------------------------------------------------
// Scratch (device globals -- the sanctioned no-alloc scratch mechanism)
// ---------------------------------------------------------------------------
__device__ float g_synwin[1024];
__device__ float g_binv[1024 * 1024];          // [m=2k+c][n], row stride 1024, zero-padded n>=1022
__device__ float g_bfwd[1024 * 1024];          // [n][m=2k+c], row stride 1024, zero rows n>=1022
__device__ float g_tf  [M1 * 1024];            // tf_frames (b,t) x WIN, row stride 1024
__device__ float g_osig[NB * OSTRIDE];         // spliced signal per batch

// ---------------------------------------------------------------------------
// f32x2 packed-FMA helpers (Blackwell FFMA2 via PTX)
// ---------------------------------------------------------------------------
__device__ __forceinline__ unsigned long long f2pack(float lo, float hi) {
    unsigned long long r;
    asm("mov.b64 %0, {%1, %2};" : "=l"(r) : "f"(lo), "f"(hi));
    return r;
}
__device__ __forceinline__ void f2unpack(unsigned long long v, float& lo, float& hi) {
    asm("mov.b64 {%0, %1}, %2;" : "=f"(lo), "=f"(hi) : "l"(v));
}
__device__ __forceinline__ unsigned long long ffma2(unsigned long long a,
                                                    unsigned long long b,
                                                    unsigned long long c) {
    unsigned long long d;
    asm("fma.rn.f32x2 %0, %1, %2, %3;" : "=l"(d) : "l"(a), "l"(b), "l"(c));
    return d;
}

// ---------------------------------------------------------------------------
// Basis fill kernels (run every launch; deterministic; ~tens of us)
// ---------------------------------------------------------------------------
__global__ void fill_synwin_kernel() {
    int n = threadIdx.x;
    if (n >= 1024) return;
    float val = 0.f;
    if (n < WIN) {
        const float c = 6.283185307179586477f / (float)WIN;
        float w = 0.5f - 0.5f * cosf(c * (float)n);
        int d = n % 400;
        float denom = 0.f;
        #pragma unroll
        for (int j = 0; j < 3; ++j) {
            int idx = d + 400 * j;
            if (idx < WIN) {
                float wj = 0.5f - 0.5f * cosf(c * (float)idx);
                denom += wj * wj;
            }
        }
        val = w / denom;
    }
    g_synwin[n] = val;
}

// B_inv[2k+c][n] = synwin[n]/WIN * w_k * {cos, -sin}(2*pi*k*n/WIN)
__global__ void fill_binv_kernel() {
    int idx = blockIdx.x * blockDim.x + threadIdx.x;   // 512*1024
    int k = idx >> 10;
    int n = idx & 1023;
    float re = 0.f, im = 0.f;
    if (n < WIN) {
        unsigned m = (unsigned)(k * n) % (unsigned)WIN;
        float ang = 6.283185307179586477f * (float)m / (float)WIN;
        float s, c;
        sincosf(ang, &s, &c);
        float wk = (k == 0 || k == 511) ? 1.f : 2.f;
        float scale = wk * g_synwin[n] * (1.0f / (float)WIN);
        re = scale * c;
        im = -scale * s;
    }
    g_binv[(2 * k) * 1024 + n]     = re;
    g_binv[(2 * k + 1) * 1024 + n] = im;
}

// B_fwd[n][2k+c] = hann[n] * {cos, -sin}(2*pi*k*n/WIN)
__global__ void fill_bfwd_kernel() {
    int idx = blockIdx.x * blockDim.x + threadIdx.x;   // 1024*512
    int k = idx & 511;
    int n = idx >> 9;
    float re = 0.f, im = 0.f;
    if (n < WIN) {
        const float cc = 6.283185307179586477f / (float)WIN;
        unsigned m = (unsigned)(k * n) % (unsigned)WIN;
        float ang = cc * (float)m;
        float s, c;
        sincosf(ang, &s, &c);
        float h = 0.5f - 0.5f * cosf(cc * (float)n);
        re = h * c;
        im = -h * s;
    }
    g_bfwd[n * 1024 + 2 * k]     = re;
    g_bfwd[n * 1024 + 2 * k + 1] = im;
}

// ---------------------------------------------------------------------------
// GEMM1: tf[(b,t)][n] = sum_m X[(b,t)][m] * Binv[m][n]
//   M=20736 (exact 162*128), K=1024, N=1022 (padded 1024)
//   X gather: x[b*XBSTR + (m>>1)*XKSTR + t*2 + (m&1)]  (float2 pairs)
// ---------------------------------------------------------------------------
__global__ void __launch_bounds__(256) gemm1_kernel(const float* __restrict__ x) {
    __shared__ __align__(16) float As[16][128];
    __shared__ __align__(16) float Bs[16][128];

    const int tid  = threadIdx.x;
    const int n0   = blockIdx.x * 128;
    const int row0 = blockIdx.y * 128;
    const int ty   = tid >> 4;
    const int tx   = tid & 15;

    unsigned long long acc[8][4] = {};   // two packed f32 each

    // A-load mapping: 32 rows x 8 k-pairs per pass, 4 passes
    const int arow = tid & 31;
    const int akp  = tid >> 5;
    const float* aptr[4];
    #pragma unroll
    for (int it = 0; it < 4; ++it) {
        int row = row0 + arow + it * 32;       // < M1 always (162*128 exact)
        int bb = row / 81;
        int tt = row - bb * 81;
        aptr[it] = x + (size_t)bb * XBSTR + (size_t)akp * XKSTR + tt * 2;
    }
    // B-load mapping: 32 float4 cols x 8 rows per pass, 2 passes
    const int bc4 = tid & 31;
    const int br  = tid >> 5;

    for (int kt = 0; kt < 1024; kt += 16) {
        #pragma unroll
        for (int it = 0; it < 4; ++it) {
            float2 v = *(const float2*)(aptr[it] + (size_t)kt * 81);
            As[2 * akp][arow + it * 32]     = v.x;
            As[2 * akp + 1][arow + it * 32] = v.y;
        }
        #pragma unroll
        for (int it = 0; it < 2; ++it) {
            int rr = br + it * 8;
            *(float4*)&Bs[rr][bc4 * 4] =
                *(const float4*)(g_binv + (size_t)(kt + rr) * 1024 + n0 + bc4 * 4);
        }
        __syncthreads();
        #pragma unroll
        for (int kk = 0; kk < 16; ++kk) {
            ulonglong2 b01 = *(const ulonglong2*)&Bs[kk][tx * 8];
            ulonglong2 b23 = *(const ulonglong2*)&Bs[kk][tx * 8 + 4];
            float4 a0 = *(const float4*)&As[kk][ty * 8];
            float4 a1 = *(const float4*)&As[kk][ty * 8 + 4];
            float av[8] = {a0.x, a0.y, a0.z, a0.w, a1.x, a1.y, a1.z, a1.w};
            #pragma unroll
            for (int i = 0; i < 8; ++i) {
                unsigned long long a2 = f2pack(av[i], av[i]);
                acc[i][0] = ffma2(a2, b01.x, acc[i][0]);
                acc[i][1] = ffma2(a2, b01.y, acc[i][1]);
                acc[i][2] = ffma2(a2, b23.x, acc[i][2]);
                acc[i][3] = ffma2(a2, b23.y, acc[i][3]);
            }
        }
        __syncthreads();
    }

    #pragma unroll
    for (int i = 0; i < 8; ++i) {
        int row = row0 + ty * 8 + i;
        float* dst = g_tf + (size_t)row * 1024;
        #pragma unroll
        for (int j4 = 0; j4 < 4; ++j4) {
            float lo, hi;
            f2unpack(acc[i][j4], lo, hi);
            int n = n0 + tx * 8 + j4 * 2;
            if (n < WIN)     dst[n]     = lo;
            if (n + 1 < WIN) dst[n + 1] = hi;
        }
    }
}

// ---------------------------------------------------------------------------
// Fold: overlap-add (<=3 frames/sample) + keep + crossfade + final keep
// ---------------------------------------------------------------------------
__device__ __forceinline__ float sigval(const float* __restrict__ tfb, int s) {
    int t1 = s / 400; if (t1 > 80) t1 = 80;
    int t0 = (s >= WIN) ? (s - (WIN - 400)) / 400 : 0;   // ceil((s-1021)/400)
    float v = 0.f;
    for (int t = t0; t <= t1; ++t)
        v += tfb[t * 1024 + (s - 400 * t)];
    return v;
}

__global__ void fold_kernel() {
    int j = blockIdx.x * blockDim.x + threadIdx.x;
    int b = blockIdx.y;
    if (j >= OUTJ) return;

    int k, r;
    if (j < 1000) { k = 0; r = j; }
    else {
        int q  = (j - 1000) / 950;
        int rr = (j - 1000) - q * 950;
        k = q + 1;
        r = 50 + rr;
    }

    float cc = 1.f, dec = 0.f, inc = 0.f;
    bool xfade = (r >= 950) && (k <= 28);
    if (xfade) {
        cc  = 0.f;
        dec = (float)(1000 - r) * 0.02f;
        inc = (float)(r - 949) * 0.02f;
    }

    const float* tfb = g_tf + (size_t)b * NT * 1024;
    float o = (cc + dec) * sigval(tfb, k * 1100 + r);
    if (xfade)
        o += inc * sigval(tfb, (k + 1) * 1100 + (r - 950));

    g_osig[(size_t)b * OSTRIDE + j] = o;
}

// ---------------------------------------------------------------------------
// GEMM2: out[(b,f)][m=2k+c] = sum_n osig[b][f*400+n] * Bfwd[n][m]
//   M=17664 (exact 138*128), K=1022 (padded 1024), N=1024
// ---------------------------------------------------------------------------
__global__ void __launch_bounds__(256) gemm2_kernel(float* __restrict__ out) {
    __shared__ __align__(16) float As[16][128];
    __shared__ __align__(16) float Bs[16][128];

    const int tid  = threadIdx.x;
    const int m0   = blockIdx.x * 128;
    const int row0 = blockIdx.y * 128;
    const int ty   = tid >> 4;
    const int tx   = tid & 15;

    unsigned long long acc[8][4] = {};

    // A-load: 64 rows x 4 float4-chunks per pass, 2 passes
    const int an4 = tid & 3;
    const int ari = tid >> 2;
    const float* aptr[2];
    #pragma unroll
    for (int it = 0; it < 2; ++it) {
        int row = row0 + ari + it * 64;        // < M2 always (138*128 exact)
        int bb = row / 69;
        int ff = row - bb * 69;
        aptr[it] = g_osig + (size_t)bb * OSTRIDE + ff * 400 + an4 * 4;
    }
    const int bc4 = tid & 31;
    const int br  = tid >> 5;

    for (int kt = 0; kt < 1024; kt += 16) {
        #pragma unroll
        for (int it = 0; it < 2; ++it) {
            float4 v = *(const float4*)(aptr[it] + kt);
            int rr = ari + it * 64;
            int c  = an4 * 4;
            As[c][rr] = v.x; As[c + 1][rr] = v.y;
            As[c + 2][rr] = v.z; As[c + 3][rr] = v.w;
        }
        #pragma unroll
        for (int it = 0; it < 2; ++it) {
            int rr = br + it * 8;
            *(float4*)&Bs[rr][bc4 * 4] =
                *(const float4*)(g_bfwd + (size_t)(kt + rr) * 1024 + m0 + bc4 * 4);
        }
        __syncthreads();
        #pragma unroll
        for (int kk = 0; kk < 16; ++kk) {
            ulonglong2 b01 = *(const ulonglong2*)&Bs[kk][tx * 8];
            ulonglong2 b23 = *(const ulonglong2*)&Bs[kk][tx * 8 + 4];
            float4 a0 = *(const float4*)&As[kk][ty * 8];
            float4 a1 = *(const float4*)&As[kk][ty * 8 + 4];
            float av[8] = {a0.x, a0.y, a0.z, a0.w, a1.x, a1.y, a1.z, a1.w};
            #pragma unroll
            for (int i = 0; i < 8; ++i) {
                unsigned long long a2 = f2pack(av[i], av[i]);
                acc[i][0] = ffma2(a2, b01.x, acc[i][0]);
                acc[i][1] = ffma2(a2, b01.y, acc[i][1]);
                acc[i][2] = ffma2(a2, b23.x, acc[i][2]);
                acc[i][3] = ffma2(a2, b23.y, acc[i][3]);
            }
        }
        __syncthreads();
    }

    // Epilogue scatter: out[b*OBSTR + k*OKSTR + f*2 + c], m = 2k+c
    #pragma unroll
    for (int i = 0; i < 8; ++i) {
        int row = row0 + ty * 8 + i;
        int bb = row / 69;
        int ff = row - bb * 69;
        float* base = out + (size_t)bb * OBSTR + ff * 2;
        #pragma unroll
        for (int j4 = 0; j4 < 4; ++j4) {
            float lo, hi;
            f2unpack(acc[i][j4], lo, hi);
            int m = m0 + tx * 8 + j4 * 2;      // even
            base[(m >> 1) * OKSTR]     = lo;   // c=0
            base[(m >> 1) * OKSTR + 1] = hi;   // c=1
        }
    }
}

// ---------------------------------------------------------------------------
// Launch
// ---------------------------------------------------------------------------
extern "C" void kernel_launch(void* const* d_in, const int* in_sizes, int n_in,
                              void* d_out, int out_size) {
    const float* x = (const float*)d_in[0];
    float* out = (float*)d_out;

    fill_synwin_kernel<<<1, 1024>>>();
    fill_binv_kernel<<<2048, 256>>>();
    fill_bfwd_kernel<<<2048, 256>>>();

    gemm1_kernel<<<dim3(8, 162), 256>>>(x);

    fold_kernel<<<dim3((OUTJ + 255) / 256, NB), 256>>>();

    gemm2_kernel<<<dim3(8, 138), 256>>>(out);
}

// round 3
// speedup vs baseline: 2.4285x; 2.4285x over previous
#include <cuda_runtime.h>
#include <cuda_fp16.h>
#include <cstdint>

// ---------------------------------------------------------------------------
// Problem constants
// ---------------------------------------------------------------------------
#define NB      256
#define NT      81
#define WIN     1022
#define NF      69
#define M1      (NB*NT)      // 20736 = 162*128
#define M2      (NB*NF)      // 17664 = 138*128
#define OUTJ    28550
#define OSTRIDE 28552
#define XBSTR   82944        // 512*81*2
#define OBSTR   70656        // 512*69*2
#define OKSTR   138          // 69*2

#define KC      32           // K per chunk
#define CH      32           // 1024/32 chunks
#define TM      128
#define TN      128

// smem layout (bytes), per buffer:
//   Ahi [128][40] fp16 = 10240 ; Alo = 10240
//   Bhi [32][136] fp16 =  8704 ; Blo =  8704
#define A_STRIDE    40
#define B_STRIDE    136
#define A_HALF_B    10240
#define B_HALF_B    8704
#define A_OFF       0
#define B_OFF       20480
#define BUF_BYTES   37888
#define SMEM_DYN    (2*BUF_BYTES)     // 75776

// ---------------------------------------------------------------------------
// Device-global scratch
// ---------------------------------------------------------------------------
__device__ float  g_synwin[1024];
__device__ __half g_binv_h[1024*1024];   // [k=2f+c][n]   (B of GEMM1, row-major)
__device__ __half g_binv_l[1024*1024];
__device__ __half g_bfwd_h[1024*1024];   // [k=n][m=2f+c] (B of GEMM2, row-major)
__device__ __half g_bfwd_l[1024*1024];
__device__ __half g_xhi[(size_t)M1*1024];
__device__ __half g_xlo[(size_t)M1*1024];
__device__ float  g_tf [(size_t)M1*1024];
__device__ float  g_osig[(size_t)NB*OSTRIDE];
__device__ __half g_fhi[(size_t)M2*1024];
__device__ __half g_flo[(size_t)M2*1024];

// ---------------------------------------------------------------------------
// PTX helpers (baseline ISA only: ldmatrix + mma.sync, sm_75/80+)
// ---------------------------------------------------------------------------
__device__ __forceinline__ uint32_t smem_to_u32(const void* p) {
    uint32_t a;
    asm("{ .reg .u64 t; cvta.to.shared.u64 t, %1; cvt.u32.u64 %0, t; }"
        : "=r"(a) : "l"(p));
    return a;
}

__device__ __forceinline__ void ldsm_x4(uint32_t* r, uint32_t addr) {
    asm volatile("ldmatrix.sync.aligned.m8n8.x4.shared.b16 {%0,%1,%2,%3}, [%4];"
        : "=r"(r[0]), "=r"(r[1]), "=r"(r[2]), "=r"(r[3]) : "r"(addr));
}
__device__ __forceinline__ void ldsm_x4_t(uint32_t* r, uint32_t addr) {
    asm volatile("ldmatrix.sync.aligned.m8n8.x4.trans.shared.b16 {%0,%1,%2,%3}, [%4];"
        : "=r"(r[0]), "=r"(r[1]), "=r"(r[2]), "=r"(r[3]) : "r"(addr));
}
__device__ __forceinline__ void mma16816(float* d, const uint32_t* a, const uint32_t* b) {
    asm volatile(
        "mma.sync.aligned.m16n8k16.row.col.f32.f16.f16.f32 "
        "{%0,%1,%2,%3}, {%4,%5,%6,%7}, {%8,%9}, {%0,%1,%2,%3};"
        : "+f"(d[0]), "+f"(d[1]), "+f"(d[2]), "+f"(d[3])
        : "r"(a[0]), "r"(a[1]), "r"(a[2]), "r"(a[3]), "r"(b[0]), "r"(b[1]));
}

// ---------------------------------------------------------------------------
// fp16 hi/lo split
// ---------------------------------------------------------------------------
__device__ __forceinline__ void f16split(float x, __half& hi, __half& lo) {
    hi = __float2half_rn(x);
    lo = __float2half_rn(x - __half2float(hi));
}

// ---------------------------------------------------------------------------
// Prep kernels
// ---------------------------------------------------------------------------
__global__ void fill_synwin_kernel() {
    int n = threadIdx.x;
    float val = 0.f;
    if (n < WIN) {
        const float c = 6.283185307179586477f / (float)WIN;
        float w = 0.5f - 0.5f * cosf(c * (float)n);
        int d = n % 400;
        float denom = 0.f;
        #pragma unroll
        for (int j = 0; j < 3; ++j) {
            int idx = d + 400 * j;
            if (idx < WIN) {
                float wj = 0.5f - 0.5f * cosf(c * (float)idx);
                denom += wj * wj;
            }
        }
        val = w / denom;
    }
    g_synwin[n] = val;
}

// g_binv[k=2f+c][n] = synwin[n]/WIN * w_f * {cos,-sin}(2*pi*f*n/WIN); 0 for n>=1022
__global__ void fill_binv_kernel() {
    int idx = blockIdx.x * blockDim.x + threadIdx.x;   // 512*1024
    int f = idx >> 10;
    int n = idx & 1023;
    float re = 0.f, im = 0.f;
    if (n < WIN) {
        unsigned m = (unsigned)(f * n) % (unsigned)WIN;
        float ang = 6.283185307179586477f * (float)m / (float)WIN;
        float s, c;
        sincosf(ang, &s, &c);
        float wk = (f == 0 || f == 511) ? 1.f : 2.f;
        float scale = wk * g_synwin[n] * (1.0f / (float)WIN);
        re = scale * c;
        im = -scale * s;
    }
    __half h, l;
    f16split(re, h, l);
    g_binv_h[(size_t)(2*f) * 1024 + n]   = h;  g_binv_l[(size_t)(2*f) * 1024 + n]   = l;
    f16split(im, h, l);
    g_binv_h[(size_t)(2*f+1) * 1024 + n] = h;  g_binv_l[(size_t)(2*f+1) * 1024 + n] = l;
}

// g_bfwd[k=n][m=2f+c] = hann[n] * {cos,-sin}(2*pi*f*n/WIN); zero rows n>=1022
__global__ void fill_bfwd_kernel() {
    int idx = blockIdx.x * blockDim.x + threadIdx.x;   // 1024*512
    int n = idx >> 9;
    int f = idx & 511;
    float re = 0.f, im = 0.f;
    if (n < WIN) {
        const float cc = 6.283185307179586477f / (float)WIN;
        unsigned m = (unsigned)(f * n) % (unsigned)WIN;
        float ang = cc * (float)m;
        float s, c;
        sincosf(ang, &s, &c);
        float h = 0.5f - 0.5f * cosf(cc * (float)n);
        re = h * c;
        im = -h * s;
    }
    __half h, l;
    f16split(re, h, l);
    g_bfwd_h[(size_t)n * 1024 + 2*f]   = h;  g_bfwd_l[(size_t)n * 1024 + 2*f]   = l;
    f16split(im, h, l);
    g_bfwd_h[(size_t)n * 1024 + 2*f+1] = h;  g_bfwd_l[(size_t)n * 1024 + 2*f+1] = l;
}

// x (B,F,T,2) -> g_xhi/g_xlo [(b,t)][2f+c]
__global__ void convert_x_kernel(const float* __restrict__ x) {
    int idx = blockIdx.x * blockDim.x + threadIdx.x;   // M1*512
    int row = idx >> 9;
    int f = idx & 511;
    int b = row / 81;
    int t = row - b * 81;
    float2 v = *(const float2*)(x + (size_t)b * XBSTR + f * 162 + t * 2);
    __half h, l;
    size_t o = (size_t)row * 1024 + 2 * f;
    f16split(v.x, h, l);  g_xhi[o] = h;     g_xlo[o] = l;
    f16split(v.y, h, l);  g_xhi[o + 1] = h; g_xlo[o + 1] = l;
}

// frames (b,f) x n -> g_fhi/g_flo, zero-padded n>=1022
__global__ void convert_frames_kernel() {
    int idx = blockIdx.x * blockDim.x + threadIdx.x;   // M2*1024
    int row = idx >> 10;
    int n = idx & 1023;
    int b = row / NF;
    int f = row - b * NF;
    float v = (n < WIN) ? g_osig[(size_t)b * OSTRIDE + f * 400 + n] : 0.f;
    __half h, l;
    f16split(v, h, l);
    g_fhi[(size_t)row * 1024 + n] = h;
    g_flo[(size_t)row * 1024 + n] = l;
}

// ---------------------------------------------------------------------------
// Fold: overlap-add + keep + crossfade + final keep
// ---------------------------------------------------------------------------
__device__ __forceinline__ float sigval(const float* __restrict__ tfb, int s) {
    int t1 = s / 400; if (t1 > 80) t1 = 80;
    int t0 = (s >= WIN) ? (s - (WIN - 400)) / 400 : 0;
    float v = 0.f;
    for (int t = t0; t <= t1; ++t)
        v += tfb[t * 1024 + (s - 400 * t)];
    return v;
}

__global__ void fold_kernel() {
    int j = blockIdx.x * blockDim.x + threadIdx.x;
    int b = blockIdx.y;
    if (j >= OUTJ) return;
    int k, r;
    if (j < 1000) { k = 0; r = j; }
    else {
        int q  = (j - 1000) / 950;
        int rr = (j - 1000) - q * 950;
        k = q + 1;
        r = 50 + rr;
    }
    float cc = 1.f, dec = 0.f, inc = 0.f;
    bool xfade = (r >= 950) && (k <= 28);
    if (xfade) {
        cc  = 0.f;
        dec = (float)(1000 - r) * 0.02f;
        inc = (float)(r - 949) * 0.02f;
    }
    const float* tfb = g_tf + (size_t)b * NT * 1024;
    float o = (cc + dec) * sigval(tfb, k * 1100 + r);
    if (xfade)
        o += inc * sigval(tfb, (k + 1) * 1100 + (r - 950));
    g_osig[(size_t)b * OSTRIDE + j] = o;
}

// ---------------------------------------------------------------------------
// Split-fp16 tensor-core GEMM via mma.sync (HMMA fallback path).
// D[128x128] fp32 per CTA = sum_K A * B, 3 products: hi*hi + hi*lo + lo*hi.
// MODE 0: A=g_x*,  B=g_binv_* -> g_tf
// MODE 1: A=g_f*,  B=g_bfwd_* -> out (scattered)
// ---------------------------------------------------------------------------
template <int MODE>
__global__ void __launch_bounds__(256) gemm_mma_kernel(float* __restrict__ outp) {
    extern __shared__ char smem[];
    const uint32_t sbase = smem_to_u32(smem);
    const int tid  = threadIdx.x;
    const int wid  = tid >> 5;
    const int lane = tid & 31;
    const int wm   = wid & 1;        // 2 warp rows (64 each)
    const int wn   = wid >> 1;       // 4 warp cols (32 each)
    const int n0   = blockIdx.x * TN;
    const int row0 = blockIdx.y * TM;

    const __half* Ah = (MODE == 0) ? g_xhi    : g_fhi;
    const __half* Al = (MODE == 0) ? g_xlo    : g_flo;
    const __half* Bh = (MODE == 0) ? g_binv_h : g_bfwd_h;
    const __half* Bl = (MODE == 0) ? g_binv_l : g_bfwd_l;

    float acc[4][4][4];
    #pragma unroll
    for (int i = 0; i < 4; ++i)
        #pragma unroll
        for (int j = 0; j < 4; ++j)
            #pragma unroll
            for (int q = 0; q < 4; ++q) acc[i][j][q] = 0.f;

    // ---- loader lane mapping ----
    const int a_row = tid >> 2, a_c8 = tid & 3;     // A: 128 rows x 4 chunks of 8
    const int b_row = tid >> 4, b_c8 = tid & 15;    // B: 32 rows x 16 chunks of 8

    auto load_chunk = [&](int c, int buf) {
        const size_t kt = (size_t)c * KC;
        const int bo = buf * BUF_BYTES;
        #pragma unroll
        for (int h = 0; h < 2; ++h) {
            const __half* src = h ? Al : Ah;
            #pragma unroll
            for (int i = 0; i < 2; ++i) {
                int row = a_row + i * 64;
                uint4 v = *(const uint4*)(src + (size_t)(row0 + row) * 1024 + kt + a_c8 * 8);
                *(uint4*)(smem + bo + A_OFF + h * A_HALF_B + row * (A_STRIDE*2) + a_c8 * 16) = v;
            }
        }
        #pragma unroll
        for (int h = 0; h < 2; ++h) {
            const __half* src = h ? Bl : Bh;
            #pragma unroll
            for (int i = 0; i < 2; ++i) {
                int row = b_row + i * 16;
                uint4 v = *(const uint4*)(src + (size_t)(kt + row) * 1024 + n0 + b_c8 * 8);
                *(uint4*)(smem + bo + B_OFF + h * B_HALF_B + row * (B_STRIDE*2) + b_c8 * 16) = v;
            }
        }
    };

    // ldmatrix lane components
    const uint32_t lrow = lane & 15;
    const uint32_t lsel = lane >> 4;

    load_chunk(0, 0);
    __syncthreads();

    for (int c = 0; c < CH; ++c) {
        if (c + 1 < CH) load_chunk(c + 1, (c + 1) & 1);

        const int bo = (c & 1) * BUF_BYTES;
        #pragma unroll
        for (int p = 0; p < 3; ++p) {
            const int ha = (p == 2) ? 1 : 0;
            const int hb = (p == 1) ? 1 : 0;
            const uint32_t aB = sbase + bo + A_OFF + ha * A_HALF_B
                                + (wm * 64 + lrow) * (A_STRIDE*2) + lsel * 16;
            const uint32_t bB = sbase + bo + B_OFF + hb * B_HALF_B
                                + lrow * (B_STRIDE*2) + (wn * 32 + lsel * 8) * 2;
            #pragma unroll
            for (int ks = 0; ks < 2; ++ks) {
                uint32_t a[4][4];
                #pragma unroll
                for (int mt = 0; mt < 4; ++mt)
                    ldsm_x4(a[mt], aB + mt * 16 * (A_STRIDE*2) + ks * 32);
                uint32_t b[2][4];
                #pragma unroll
                for (int bt = 0; bt < 2; ++bt)
                    ldsm_x4_t(b[bt], bB + bt * 32 + ks * 16 * (B_STRIDE*2));
                #pragma unroll
                for (int mt = 0; mt < 4; ++mt)
                    #pragma unroll
                    for (int nt = 0; nt < 4; ++nt)
                        mma16816(acc[mt][nt], a[mt], &b[nt >> 1][(nt & 1) * 2]);
            }
        }
        __syncthreads();
    }

    // ---- epilogue ----
    #pragma unroll
    for (int mt = 0; mt < 4; ++mt) {
        const int r0 = row0 + wm * 64 + mt * 16 + (lane >> 2);
        #pragma unroll
        for (int half = 0; half < 2; ++half) {
            const int r = r0 + half * 8;
            int bb = 0, ff = 0;
            if (MODE == 1) { bb = r / NF; ff = r - bb * NF; }
            #pragma unroll
            for (int nt = 0; nt < 4; ++nt) {
                const int ccol = n0 + wn * 32 + nt * 8 + (lane & 3) * 2;
                float2 v = make_float2(acc[mt][nt][half * 2], acc[mt][nt][half * 2 + 1]);
                if (MODE == 0) {
                    *(float2*)(g_tf + (size_t)r * 1024 + ccol) = v;
                } else {
                    // col m = ccol (even): k = m>>1, c = {0,1}
                    *(float2*)(outp + (size_t)bb * OBSTR + (ccol >> 1) * OKSTR + ff * 2) = v;
                }
            }
        }
    }
}

// ---------------------------------------------------------------------------
// Launch
// ---------------------------------------------------------------------------
extern "C" void kernel_launch(void* const* d_in, const int* in_sizes, int n_in,
                              void* d_out, int out_size) {
    const float* x = (const float*)d_in[0];
    float* out = (float*)d_out;

    cudaFuncSetAttribute(gemm_mma_kernel<0>,
                         cudaFuncAttributeMaxDynamicSharedMemorySize, SMEM_DYN);
    cudaFuncSetAttribute(gemm_mma_kernel<1>,
                         cudaFuncAttributeMaxDynamicSharedMemorySize, SMEM_DYN);

    fill_synwin_kernel<<<1, 1024>>>();
    fill_binv_kernel<<<2048, 256>>>();
    fill_bfwd_kernel<<<2048, 256>>>();
    convert_x_kernel<<<(M1 * 512) / 256, 256>>>(x);

    gemm_mma_kernel<0><<<dim3(8, 162), 256, SMEM_DYN>>>(nullptr);

    fold_kernel<<<dim3((OUTJ + 255) / 256, NB), 256>>>();
    convert_frames_kernel<<<(M2 * 1024) / 256, 256>>>();

    gemm_mma_kernel<1><<<dim3(8, 138), 256, SMEM_DYN>>>(out);
}

// round 4
// speedup vs baseline: 3.4233x; 1.4096x over previous
#include <cuda_runtime.h>
#include <cuda_fp16.h>
#include <cstdint>

// ---------------------------------------------------------------------------
// Problem constants
// ---------------------------------------------------------------------------
#define NB      256
#define NT      81
#define WIN     1022
#define NF      69
#define M1      (NB*NT)      // 20736 = 162*128
#define M2      (NB*NF)      // 17664 = 138*128
#define OUTJ    28550
#define OSTRIDE 28552
#define XBSTR   82944        // 512*81*2
#define OBSTR   70656        // 512*69*2
#define OKSTR   138          // 69*2

#define KC      32           // K per chunk
#define CH      32           // 1024/32 chunks
#define TM      128
#define TN      128
#define STAGES  3

// smem per stage (bytes): A[128][40] fp16 = 10240 ; Bh[32][136] = 8704 ; Bl = 8704
#define A_STRIDE    40       // halfs
#define B_STRIDEB   272      // bytes (136 halfs)
#define A_OFF       0
#define BH_OFF      10240
#define BL_OFF      18944
#define STAGE_BYTES 27648
#define SMEM_DYN    (STAGES*STAGE_BYTES)   // 82944

// ---------------------------------------------------------------------------
// Device-global scratch
// ---------------------------------------------------------------------------
__device__ float  g_synwin[1024];
__device__ __half g_binv_h[1024*1024];   // [k=2f+c][n]   (B of GEMM1, row-major)
__device__ __half g_binv_l[1024*1024];
__device__ __half g_bfwd_h[1024*1024];   // [k=n][m=2f+c] (B of GEMM2, row-major)
__device__ __half g_bfwd_l[1024*1024];
__device__ __half g_xhi[(size_t)M1*1024];
__device__ float  g_tf [(size_t)M1*1024];
__device__ float  g_osig[(size_t)NB*OSTRIDE];
__device__ __half g_fhi[(size_t)M2*1024];

// ---------------------------------------------------------------------------
// PTX helpers (baseline ISA: ldmatrix + mma.sync + cp.async, sm_80+)
// ---------------------------------------------------------------------------
__device__ __forceinline__ uint32_t smem_to_u32(const void* p) {
    uint32_t a;
    asm("{ .reg .u64 t; cvta.to.shared.u64 t, %1; cvt.u32.u64 %0, t; }"
        : "=r"(a) : "l"(p));
    return a;
}
__device__ __forceinline__ void ldsm_x4(uint32_t* r, uint32_t addr) {
    asm volatile("ldmatrix.sync.aligned.m8n8.x4.shared.b16 {%0,%1,%2,%3}, [%4];"
        : "=r"(r[0]), "=r"(r[1]), "=r"(r[2]), "=r"(r[3]) : "r"(addr));
}
__device__ __forceinline__ void ldsm_x4_t(uint32_t* r, uint32_t addr) {
    asm volatile("ldmatrix.sync.aligned.m8n8.x4.trans.shared.b16 {%0,%1,%2,%3}, [%4];"
        : "=r"(r[0]), "=r"(r[1]), "=r"(r[2]), "=r"(r[3]) : "r"(addr));
}
__device__ __forceinline__ void mma16816(float* d, const uint32_t* a, const uint32_t* b) {
    asm volatile(
        "mma.sync.aligned.m16n8k16.row.col.f32.f16.f16.f32 "
        "{%0,%1,%2,%3}, {%4,%5,%6,%7}, {%8,%9}, {%0,%1,%2,%3};"
        : "+f"(d[0]), "+f"(d[1]), "+f"(d[2]), "+f"(d[3])
        : "r"(a[0]), "r"(a[1]), "r"(a[2]), "r"(a[3]), "r"(b[0]), "r"(b[1]));
}
__device__ __forceinline__ void cp16(uint32_t saddr, const void* gaddr) {
    asm volatile("cp.async.cg.shared.global [%0], [%1], 16;"
        :: "r"(saddr), "l"(gaddr));
}
#define CP_COMMIT() asm volatile("cp.async.commit_group;" ::: "memory")
#define CP_WAIT(N)  asm volatile("cp.async.wait_group %0;" :: "n"(N) : "memory")

// ---------------------------------------------------------------------------
// fp16 hi/lo split
// ---------------------------------------------------------------------------
__device__ __forceinline__ void f16split(float x, __half& hi, __half& lo) {
    hi = __float2half_rn(x);
    lo = __float2half_rn(x - __half2float(hi));
}

// ---------------------------------------------------------------------------
// Prep kernels
// ---------------------------------------------------------------------------
__global__ void fill_synwin_kernel() {
    int n = threadIdx.x;
    float val = 0.f;
    if (n < WIN) {
        const float c = 6.283185307179586477f / (float)WIN;
        float w = 0.5f - 0.5f * cosf(c * (float)n);
        int d = n % 400;
        float denom = 0.f;
        #pragma unroll
        for (int j = 0; j < 3; ++j) {
            int idx = d + 400 * j;
            if (idx < WIN) {
                float wj = 0.5f - 0.5f * cosf(c * (float)idx);
                denom += wj * wj;
            }
        }
        val = w / denom;
    }
    g_synwin[n] = val;
}

// g_binv[k=2f+c][n] = synwin[n]/WIN * w_f * {cos,-sin}(2*pi*f*n/WIN); 0 for n>=1022
__global__ void fill_binv_kernel() {
    int idx = blockIdx.x * blockDim.x + threadIdx.x;   // 512*1024
    int f = idx >> 10;
    int n = idx & 1023;
    float re = 0.f, im = 0.f;
    if (n < WIN) {
        unsigned m = (unsigned)(f * n) % (unsigned)WIN;
        float ang = 6.283185307179586477f * (float)m / (float)WIN;
        float s, c;
        sincosf(ang, &s, &c);
        float wk = (f == 0 || f == 511) ? 1.f : 2.f;
        float scale = wk * g_synwin[n] * (1.0f / (float)WIN);
        re = scale * c;
        im = -scale * s;
    }
    __half h, l;
    f16split(re, h, l);
    g_binv_h[(size_t)(2*f) * 1024 + n]   = h;  g_binv_l[(size_t)(2*f) * 1024 + n]   = l;
    f16split(im, h, l);
    g_binv_h[(size_t)(2*f+1) * 1024 + n] = h;  g_binv_l[(size_t)(2*f+1) * 1024 + n] = l;
}

// g_bfwd[k=n][m=2f+c] = hann[n] * {cos,-sin}(2*pi*f*n/WIN); zero rows n>=1022
__global__ void fill_bfwd_kernel() {
    int idx = blockIdx.x * blockDim.x + threadIdx.x;   // 1024*512
    int n = idx >> 9;
    int f = idx & 511;
    float re = 0.f, im = 0.f;
    if (n < WIN) {
        const float cc = 6.283185307179586477f / (float)WIN;
        unsigned m = (unsigned)(f * n) % (unsigned)WIN;
        float ang = cc * (float)m;
        float s, c;
        sincosf(ang, &s, &c);
        float h = 0.5f - 0.5f * cosf(cc * (float)n);
        re = h * c;
        im = -h * s;
    }
    __half h, l;
    f16split(re, h, l);
    g_bfwd_h[(size_t)n * 1024 + 2*f]   = h;  g_bfwd_l[(size_t)n * 1024 + 2*f]   = l;
    f16split(im, h, l);
    g_bfwd_h[(size_t)n * 1024 + 2*f+1] = h;  g_bfwd_l[(size_t)n * 1024 + 2*f+1] = l;
}

// x (B,F,T,2) -> g_xhi [(b,t)][2f+c]
__global__ void convert_x_kernel(const float* __restrict__ x) {
    int idx = blockIdx.x * blockDim.x + threadIdx.x;   // M1*512
    int row = idx >> 9;
    int f = idx & 511;
    int b = row / 81;
    int t = row - b * 81;
    float2 v = *(const float2*)(x + (size_t)b * XBSTR + f * 162 + t * 2);
    size_t o = (size_t)row * 1024 + 2 * f;
    __half2* dst = (__half2*)(g_xhi + o);
    *dst = __floats2half2_rn(v.x, v.y);
}

// frames (b,f) x n -> g_fhi, zero-padded n>=1022
__global__ void convert_frames_kernel() {
    int idx = blockIdx.x * blockDim.x + threadIdx.x;   // M2*1024
    int row = idx >> 10;
    int n = idx & 1023;
    int b = row / NF;
    int f = row - b * NF;
    float v = (n < WIN) ? g_osig[(size_t)b * OSTRIDE + f * 400 + n] : 0.f;
    g_fhi[(size_t)row * 1024 + n] = __float2half_rn(v);
}

// ---------------------------------------------------------------------------
// Fold: overlap-add + keep + crossfade + final keep
// ---------------------------------------------------------------------------
__device__ __forceinline__ float sigval(const float* __restrict__ tfb, int s) {
    int t1 = s / 400; if (t1 > 80) t1 = 80;
    int t0 = (s >= WIN) ? (s - (WIN - 400)) / 400 : 0;
    float v = 0.f;
    for (int t = t0; t <= t1; ++t)
        v += tfb[t * 1024 + (s - 400 * t)];
    return v;
}

__global__ void fold_kernel() {
    int j = blockIdx.x * blockDim.x + threadIdx.x;
    int b = blockIdx.y;
    if (j >= OUTJ) return;
    int k, r;
    if (j < 1000) { k = 0; r = j; }
    else {
        int q  = (j - 1000) / 950;
        int rr = (j - 1000) - q * 950;
        k = q + 1;
        r = 50 + rr;
    }
    float cc = 1.f, dec = 0.f, inc = 0.f;
    bool xfade = (r >= 950) && (k <= 28);
    if (xfade) {
        cc  = 0.f;
        dec = (float)(1000 - r) * 0.02f;
        inc = (float)(r - 949) * 0.02f;
    }
    const float* tfb = g_tf + (size_t)b * NT * 1024;
    float o = (cc + dec) * sigval(tfb, k * 1100 + r);
    if (xfade)
        o += inc * sigval(tfb, (k + 1) * 1100 + (r - 950));
    g_osig[(size_t)b * OSTRIDE + j] = o;
}

// ---------------------------------------------------------------------------
// Split-fp16 tensor-core GEMM via mma.sync, cp.async 3-stage pipeline.
// D[128x128] fp32 per CTA; 2 products: A_hi*B_hi + A_hi*B_lo.
// MODE 0: A=g_xhi, B=g_binv_* -> g_tf
// MODE 1: A=g_fhi, B=g_bfwd_* -> out (scattered)
// ---------------------------------------------------------------------------
template <int MODE>
__global__ void __launch_bounds__(256) gemm_mma_kernel(float* __restrict__ outp) {
    extern __shared__ char smem[];
    const uint32_t sbase = smem_to_u32(smem);
    const int tid  = threadIdx.x;
    const int wid  = tid >> 5;
    const int lane = tid & 31;
    const int wm   = wid & 1;        // 2 warp rows (64 each)
    const int wn   = wid >> 1;       // 4 warp cols (32 each)
    const int n0   = blockIdx.x * TN;
    const int row0 = blockIdx.y * TM;

    const __half* Ah = (MODE == 0) ? g_xhi    : g_fhi;
    const __half* Bh = (MODE == 0) ? g_binv_h : g_bfwd_h;
    const __half* Bl = (MODE == 0) ? g_binv_l : g_bfwd_l;

    float acc[4][4][4];
    #pragma unroll
    for (int i = 0; i < 4; ++i)
        #pragma unroll
        for (int j = 0; j < 4; ++j)
            #pragma unroll
            for (int q = 0; q < 4; ++q) acc[i][j][q] = 0.f;

    // loader lane mapping (per thread: 2 A units + 2x2 B units, 16B each)
    const int a_row = tid >> 2, a_seg = tid & 3;    // A: 128 rows x 4 segs (u = tid, tid+256 -> rows +64)
    const int b_row = tid >> 4, b_seg = tid & 15;   // B: 32 rows x 16 segs (u = tid, tid+256 -> rows +16)

    auto load_chunk = [&](int c, int buf) {
        const size_t kt = (size_t)c * KC;
        const uint32_t sa = sbase + buf * STAGE_BYTES;
        #pragma unroll
        for (int i = 0; i < 2; ++i) {
            int row = a_row + i * 64;
            cp16(sa + A_OFF + row * (A_STRIDE*2) + a_seg * 16,
                 Ah + (size_t)(row0 + row) * 1024 + kt + a_seg * 8);
        }
        #pragma unroll
        for (int h = 0; h < 2; ++h) {
            const __half* src = h ? Bl : Bh;
            const uint32_t off = h ? BL_OFF : BH_OFF;
            #pragma unroll
            for (int i = 0; i < 2; ++i) {
                int row = b_row + i * 16;
                cp16(sa + off + row * B_STRIDEB + b_seg * 16,
                     src + (size_t)(kt + row) * 1024 + n0 + b_seg * 8);
            }
        }
    };

    const uint32_t lrow = lane & 15;
    const uint32_t lsel = lane >> 4;

    // prologue: fill STAGES-1 buffers
    #pragma unroll
    for (int s = 0; s < STAGES - 1; ++s) {
        load_chunk(s, s);
        CP_COMMIT();
    }

    for (int c = 0; c < CH; ++c) {
        CP_WAIT(STAGES - 2);
        __syncthreads();

        // issue loads for chunk c+STAGES-1 into buffer (c-1)%STAGES (safe: consumed at c-1)
        if (c + STAGES - 1 < CH)
            load_chunk(c + STAGES - 1, (c + STAGES - 1) % STAGES);
        CP_COMMIT();

        const int buf = c % STAGES;
        const uint32_t sb = sbase + buf * STAGE_BYTES;
        const uint32_t aB = sb + A_OFF + (wm * 64 + lrow) * (A_STRIDE*2) + lsel * 16;
        const uint32_t bB = sb + BH_OFF + lrow * B_STRIDEB + (wn * 32 + lsel * 8) * 2;

        #pragma unroll
        for (int ks = 0; ks < 2; ++ks) {
            uint32_t a[4][4];
            #pragma unroll
            for (int mt = 0; mt < 4; ++mt)
                ldsm_x4(a[mt], aB + mt * 16 * (A_STRIDE*2) + ks * 32);
            #pragma unroll
            for (int p = 0; p < 2; ++p) {
                uint32_t b[2][4];
                const uint32_t pb = bB + p * (BL_OFF - BH_OFF) + ks * 16 * B_STRIDEB;
                #pragma unroll
                for (int bt = 0; bt < 2; ++bt)
                    ldsm_x4_t(b[bt], pb + bt * 32);
                #pragma unroll
                for (int mt = 0; mt < 4; ++mt)
                    #pragma unroll
                    for (int nt = 0; nt < 4; ++nt)
                        mma16816(acc[mt][nt], a[mt], &b[nt >> 1][(nt & 1) * 2]);
            }
        }
    }

    // ---- epilogue ----
    #pragma unroll
    for (int mt = 0; mt < 4; ++mt) {
        const int r0 = row0 + wm * 64 + mt * 16 + (lane >> 2);
        #pragma unroll
        for (int half = 0; half < 2; ++half) {
            const int r = r0 + half * 8;
            int bb = 0, ff = 0;
            if (MODE == 1) { bb = r / NF; ff = r - bb * NF; }
            #pragma unroll
            for (int nt = 0; nt < 4; ++nt) {
                const int ccol = n0 + wn * 32 + nt * 8 + (lane & 3) * 2;
                float2 v = make_float2(acc[mt][nt][half * 2], acc[mt][nt][half * 2 + 1]);
                if (MODE == 0) {
                    *(float2*)(g_tf + (size_t)r * 1024 + ccol) = v;
                } else {
                    *(float2*)(outp + (size_t)bb * OBSTR + (ccol >> 1) * OKSTR + ff * 2) = v;
                }
            }
        }
    }
}

// ---------------------------------------------------------------------------
// Launch
// ---------------------------------------------------------------------------
extern "C" void kernel_launch(void* const* d_in, const int* in_sizes, int n_in,
                              void* d_out, int out_size) {
    const float* x = (const float*)d_in[0];
    float* out = (float*)d_out;

    cudaFuncSetAttribute(gemm_mma_kernel<0>,
                         cudaFuncAttributeMaxDynamicSharedMemorySize, SMEM_DYN);
    cudaFuncSetAttribute(gemm_mma_kernel<1>,
                         cudaFuncAttributeMaxDynamicSharedMemorySize, SMEM_DYN);

    fill_synwin_kernel<<<1, 1024>>>();
    fill_binv_kernel<<<2048, 256>>>();
    fill_bfwd_kernel<<<2048, 256>>>();
    convert_x_kernel<<<(M1 * 512) / 256, 256>>>(x);

    gemm_mma_kernel<0><<<dim3(8, 162), 256, SMEM_DYN>>>(nullptr);

    fold_kernel<<<dim3((OUTJ + 255) / 256, NB), 256>>>();
    convert_frames_kernel<<<(M2 * 1024) / 256, 256>>>();

    gemm_mma_kernel<1><<<dim3(8, 138), 256, SMEM_DYN>>>(out);
}

// round 5
// speedup vs baseline: 3.9120x; 1.1428x over previous
#include <cuda_runtime.h>
#include <cuda_fp16.h>
#include <cstdint>

// ---------------------------------------------------------------------------
// Problem constants
// ---------------------------------------------------------------------------
#define NB      256
#define NT      81
#define WIN     1022
#define NF      69
#define M1      (NB*NT)      // 20736 = 162*128
#define M2      (NB*NF)      // 17664 = 138*128
#define OUTJ    28550
#define XBSTR   82944        // 512*81*2
#define OBSTR   70656        // 512*69*2
#define OKSTR   138          // 69*2

#define KC      32           // K per chunk
#define CH      32           // 1024/32 chunks
#define TM      128
#define TN      128
#define STAGES  3

// smem per stage (bytes): A[128][40] fp16 = 10240 ; Bh[32][136] = 8704 ; Bl = 8704
#define A_STRIDE    40       // halfs
#define B_STRIDEB   272      // bytes (136 halfs)
#define A_OFF       0
#define BH_OFF      10240
#define BL_OFF      18944
#define STAGE_BYTES 27648
#define SMEM_DYN    (STAGES*STAGE_BYTES)   // 82944

// ---------------------------------------------------------------------------
// Device-global scratch
// ---------------------------------------------------------------------------
__device__ float  g_synwin[1024];
__device__ __half g_binv_h[1024*1024];   // [k=2f+c][n]   (B of GEMM1)
__device__ __half g_binv_l[1024*1024];
__device__ __half g_bfwd_h[1024*1024];   // [k=n][m=2f+c] (B of GEMM2)
__device__ __half g_bfwd_l[1024*1024];
__device__ __half g_xhi[(size_t)M1*1024];
__device__ __half g_tf [(size_t)M1*1024];   // iSTFT frames (fp16)
__device__ __half g_fhi[(size_t)M2*1024];   // STFT input frames (fp16)

// ---------------------------------------------------------------------------
// PTX helpers (baseline ISA: ldmatrix + mma.sync + cp.async, sm_80+)
// ---------------------------------------------------------------------------
__device__ __forceinline__ uint32_t smem_to_u32(const void* p) {
    uint32_t a;
    asm("{ .reg .u64 t; cvta.to.shared.u64 t, %1; cvt.u32.u64 %0, t; }"
        : "=r"(a) : "l"(p));
    return a;
}
__device__ __forceinline__ void ldsm_x4(uint32_t* r, uint32_t addr) {
    asm volatile("ldmatrix.sync.aligned.m8n8.x4.shared.b16 {%0,%1,%2,%3}, [%4];"
        : "=r"(r[0]), "=r"(r[1]), "=r"(r[2]), "=r"(r[3]) : "r"(addr));
}
__device__ __forceinline__ void ldsm_x4_t(uint32_t* r, uint32_t addr) {
    asm volatile("ldmatrix.sync.aligned.m8n8.x4.trans.shared.b16 {%0,%1,%2,%3}, [%4];"
        : "=r"(r[0]), "=r"(r[1]), "=r"(r[2]), "=r"(r[3]) : "r"(addr));
}
__device__ __forceinline__ void mma16816(float* d, const uint32_t* a, const uint32_t* b) {
    asm volatile(
        "mma.sync.aligned.m16n8k16.row.col.f32.f16.f16.f32 "
        "{%0,%1,%2,%3}, {%4,%5,%6,%7}, {%8,%9}, {%0,%1,%2,%3};"
        : "+f"(d[0]), "+f"(d[1]), "+f"(d[2]), "+f"(d[3])
        : "r"(a[0]), "r"(a[1]), "r"(a[2]), "r"(a[3]), "r"(b[0]), "r"(b[1]));
}
__device__ __forceinline__ void cp16(uint32_t saddr, const void* gaddr) {
    asm volatile("cp.async.cg.shared.global [%0], [%1], 16;"
        :: "r"(saddr), "l"(gaddr));
}
#define CP_COMMIT() asm volatile("cp.async.commit_group;" ::: "memory")
#define CP_WAIT(N)  asm volatile("cp.async.wait_group %0;" :: "n"(N) : "memory")

// ---------------------------------------------------------------------------
// fp16 hi/lo split
// ---------------------------------------------------------------------------
__device__ __forceinline__ void f16split(float x, __half& hi, __half& lo) {
    hi = __float2half_rn(x);
    lo = __float2half_rn(x - __half2float(hi));
}

// ---------------------------------------------------------------------------
// Prep kernels
// ---------------------------------------------------------------------------
__global__ void fill_synwin_kernel() {
    int n = threadIdx.x;
    float val = 0.f;
    if (n < WIN) {
        const float c = 6.283185307179586477f / (float)WIN;
        float w = 0.5f - 0.5f * cosf(c * (float)n);
        int d = n % 400;
        float denom = 0.f;
        #pragma unroll
        for (int j = 0; j < 3; ++j) {
            int idx = d + 400 * j;
            if (idx < WIN) {
                float wj = 0.5f - 0.5f * cosf(c * (float)idx);
                denom += wj * wj;
            }
        }
        val = w / denom;
    }
    g_synwin[n] = val;
}

// g_binv[k=2f+c][n] = synwin[n]/WIN * w_f * {cos,-sin}(2*pi*f*n/WIN); 0 for n>=1022
__global__ void fill_binv_kernel() {
    int idx = blockIdx.x * blockDim.x + threadIdx.x;   // 512*1024
    int f = idx >> 10;
    int n = idx & 1023;
    float re = 0.f, im = 0.f;
    if (n < WIN) {
        unsigned m = (unsigned)(f * n) % (unsigned)WIN;
        float ang = 6.283185307179586477f * (float)m / (float)WIN;
        float s, c;
        __sincosf(ang, &s, &c);
        float wk = (f == 0 || f == 511) ? 1.f : 2.f;
        float scale = wk * g_synwin[n] * (1.0f / (float)WIN);
        re = scale * c;
        im = -scale * s;
    }
    __half h, l;
    f16split(re, h, l);
    g_binv_h[(size_t)(2*f) * 1024 + n]   = h;  g_binv_l[(size_t)(2*f) * 1024 + n]   = l;
    f16split(im, h, l);
    g_binv_h[(size_t)(2*f+1) * 1024 + n] = h;  g_binv_l[(size_t)(2*f+1) * 1024 + n] = l;
}

// g_bfwd[k=n][m=2f+c] = hann[n] * {cos,-sin}(2*pi*f*n/WIN); zero rows n>=1022
__global__ void fill_bfwd_kernel() {
    int idx = blockIdx.x * blockDim.x + threadIdx.x;   // 1024*512
    int n = idx >> 9;
    int f = idx & 511;
    float re = 0.f, im = 0.f;
    if (n < WIN) {
        const float cc = 6.283185307179586477f / (float)WIN;
        unsigned m = (unsigned)(f * n) % (unsigned)WIN;
        float ang = cc * (float)m;
        float s, c;
        __sincosf(ang, &s, &c);
        float h = 0.5f - 0.5f * __cosf(cc * (float)n);
        re = h * c;
        im = -h * s;
    }
    __half h, l;
    f16split(re, h, l);
    g_bfwd_h[(size_t)n * 1024 + 2*f]   = h;  g_bfwd_l[(size_t)n * 1024 + 2*f]   = l;
    f16split(im, h, l);
    g_bfwd_h[(size_t)n * 1024 + 2*f+1] = h;  g_bfwd_l[(size_t)n * 1024 + 2*f+1] = l;
}

// x (B,F,T,2) -> g_xhi [(b,t)][2f+c]  -- smem tile transpose, coalesced both ways
__global__ void __launch_bounds__(256) convert_x_kernel(const float* __restrict__ x) {
    __shared__ __half2 tile[64 * 81];
    const int b  = blockIdx.y;
    const int f0 = blockIdx.x * 64;
    const float* xb = x + (size_t)b * XBSTR;
    for (int i = threadIdx.x; i < 64 * 81; i += 256) {
        int fi = i / 81, t = i - fi * 81;
        float2 v = *(const float2*)(xb + (size_t)(f0 + fi) * 162 + t * 2);
        tile[fi * 81 + t] = __floats2half2_rn(v.x, v.y);
    }
    __syncthreads();
    for (int i = threadIdx.x; i < 64 * 81; i += 256) {
        int t = i >> 6, fi = i & 63;
        *(__half2*)(g_xhi + (size_t)(b * 81 + t) * 1024 + 2 * (f0 + fi)) = tile[fi * 81 + t];
    }
}

// ---------------------------------------------------------------------------
// Fold (fused): overlap-add + keep + crossfade + final keep, then scatter the
// sample directly into every STFT frame row that contains it (fp16).
// ---------------------------------------------------------------------------
__device__ __forceinline__ float sigval(const __half* __restrict__ tfb, int s) {
    int t1 = s / 400; if (t1 > 80) t1 = 80;
    int t0 = (s >= WIN) ? (s - (WIN - 400)) / 400 : 0;
    float v = 0.f;
    for (int t = t0; t <= t1; ++t)
        v += __half2float(tfb[t * 1024 + (s - 400 * t)]);
    return v;
}

__global__ void fold_kernel() {
    int j = blockIdx.x * blockDim.x + threadIdx.x;
    int b = blockIdx.y;
    if (j >= OUTJ) return;
    int k, r;
    if (j < 1000) { k = 0; r = j; }
    else {
        int q  = (j - 1000) / 950;
        int rr = (j - 1000) - q * 950;
        k = q + 1;
        r = 50 + rr;
    }
    float cc = 1.f, dec = 0.f, inc = 0.f;
    bool xfade = (r >= 950) && (k <= 28);
    if (xfade) {
        cc  = 0.f;
        dec = (float)(1000 - r) * 0.02f;
        inc = (float)(r - 949) * 0.02f;
    }
    const __half* tfb = g_tf + (size_t)b * NT * 1024;
    float o = (cc + dec) * sigval(tfb, k * 1100 + r);
    if (xfade)
        o += inc * sigval(tfb, (k + 1) * 1100 + (r - 950));

    // scatter into frames: rows f with f*400 <= j <= f*400+1021
    int fmax = j / 400; if (fmax > NF - 1) fmax = NF - 1;
    int fmin = (j >= WIN) ? (j - WIN) / 400 + 1 : 0;
    __half hv = __float2half_rn(o);
    __half* fb = g_fhi + (size_t)b * NF * 1024;
    for (int f = fmin; f <= fmax; ++f)
        fb[f * 1024 + (j - 400 * f)] = hv;
}

// zero the 2-column padding of g_fhi (n = 1022, 1023)
__global__ void pad_frames_kernel() {
    int idx = blockIdx.x * blockDim.x + threadIdx.x;
    if (idx >= M2) return;
    *(__half2*)(g_fhi + (size_t)idx * 1024 + WIN) = __half2{};
}

// ---------------------------------------------------------------------------
// Split-fp16 tensor-core GEMM via mma.sync, cp.async 3-stage pipeline.
// D[128x128] fp32 per CTA; 2 products: A_hi*B_hi + A_hi*B_lo.
// MODE 0: A=g_xhi, B=g_binv_* -> g_tf (fp16)
// MODE 1: A=g_fhi, B=g_bfwd_* -> out (fp32, scattered)
// ---------------------------------------------------------------------------
template <int MODE>
__global__ void __launch_bounds__(256) gemm_mma_kernel(float* __restrict__ outp) {
    extern __shared__ char smem[];
    const uint32_t sbase = smem_to_u32(smem);
    const int tid  = threadIdx.x;
    const int wid  = tid >> 5;
    const int lane = tid & 31;
    const int wm   = wid & 1;        // 2 warp rows (64 each)
    const int wn   = wid >> 1;       // 4 warp cols (32 each)
    const int n0   = blockIdx.x * TN;
    const int row0 = blockIdx.y * TM;

    const __half* Ah = (MODE == 0) ? g_xhi    : g_fhi;
    const __half* Bh = (MODE == 0) ? g_binv_h : g_bfwd_h;
    const __half* Bl = (MODE == 0) ? g_binv_l : g_bfwd_l;

    float acc[4][4][4];
    #pragma unroll
    for (int i = 0; i < 4; ++i)
        #pragma unroll
        for (int j = 0; j < 4; ++j)
            #pragma unroll
            for (int q = 0; q < 4; ++q) acc[i][j][q] = 0.f;

    const int a_row = tid >> 2, a_seg = tid & 3;
    const int b_row = tid >> 4, b_seg = tid & 15;

    auto load_chunk = [&](int c, int buf) {
        const size_t kt = (size_t)c * KC;
        const uint32_t sa = sbase + buf * STAGE_BYTES;
        #pragma unroll
        for (int i = 0; i < 2; ++i) {
            int row = a_row + i * 64;
            cp16(sa + A_OFF + row * (A_STRIDE*2) + a_seg * 16,
                 Ah + (size_t)(row0 + row) * 1024 + kt + a_seg * 8);
        }
        #pragma unroll
        for (int h = 0; h < 2; ++h) {
            const __half* src = h ? Bl : Bh;
            const uint32_t off = h ? BL_OFF : BH_OFF;
            #pragma unroll
            for (int i = 0; i < 2; ++i) {
                int row = b_row + i * 16;
                cp16(sa + off + row * B_STRIDEB + b_seg * 16,
                     src + (size_t)(kt + row) * 1024 + n0 + b_seg * 8);
            }
        }
    };

    const uint32_t lrow = lane & 15;
    const uint32_t lsel = lane >> 4;

    #pragma unroll
    for (int s = 0; s < STAGES - 1; ++s) {
        load_chunk(s, s);
        CP_COMMIT();
    }

    for (int c = 0; c < CH; ++c) {
        CP_WAIT(STAGES - 2);
        __syncthreads();

        if (c + STAGES - 1 < CH)
            load_chunk(c + STAGES - 1, (c + STAGES - 1) % STAGES);
        CP_COMMIT();

        const int buf = c % STAGES;
        const uint32_t sb = sbase + buf * STAGE_BYTES;
        const uint32_t aB = sb + A_OFF + (wm * 64 + lrow) * (A_STRIDE*2) + lsel * 16;
        const uint32_t bB = sb + BH_OFF + lrow * B_STRIDEB + (wn * 32 + lsel * 8) * 2;

        #pragma unroll
        for (int ks = 0; ks < 2; ++ks) {
            uint32_t a[4][4];
            #pragma unroll
            for (int mt = 0; mt < 4; ++mt)
                ldsm_x4(a[mt], aB + mt * 16 * (A_STRIDE*2) + ks * 32);
            #pragma unroll
            for (int p = 0; p < 2; ++p) {
                uint32_t b[2][4];
                const uint32_t pb = bB + p * (BL_OFF - BH_OFF) + ks * 16 * B_STRIDEB;
                #pragma unroll
                for (int bt = 0; bt < 2; ++bt)
                    ldsm_x4_t(b[bt], pb + bt * 32);
                #pragma unroll
                for (int mt = 0; mt < 4; ++mt)
                    #pragma unroll
                    for (int nt = 0; nt < 4; ++nt)
                        mma16816(acc[mt][nt], a[mt], &b[nt >> 1][(nt & 1) * 2]);
            }
        }
    }

    // ---- epilogue ----
    #pragma unroll
    for (int mt = 0; mt < 4; ++mt) {
        const int r0 = row0 + wm * 64 + mt * 16 + (lane >> 2);
        #pragma unroll
        for (int half = 0; half < 2; ++half) {
            const int r = r0 + half * 8;
            int bb = 0, ff = 0;
            if (MODE == 1) { bb = r / NF; ff = r - bb * NF; }
            #pragma unroll
            for (int nt = 0; nt < 4; ++nt) {
                const int ccol = n0 + wn * 32 + nt * 8 + (lane & 3) * 2;
                float v0 = acc[mt][nt][half * 2], v1 = acc[mt][nt][half * 2 + 1];
                if (MODE == 0) {
                    *(__half2*)(g_tf + (size_t)r * 1024 + ccol) = __floats2half2_rn(v0, v1);
                } else {
                    *(float2*)(outp + (size_t)bb * OBSTR + (ccol >> 1) * OKSTR + ff * 2)
                        = make_float2(v0, v1);
                }
            }
        }
    }
}

// ---------------------------------------------------------------------------
// Launch
// ---------------------------------------------------------------------------
extern "C" void kernel_launch(void* const* d_in, const int* in_sizes, int n_in,
                              void* d_out, int out_size) {
    const float* x = (const float*)d_in[0];
    float* out = (float*)d_out;

    cudaFuncSetAttribute(gemm_mma_kernel<0>,
                         cudaFuncAttributeMaxDynamicSharedMemorySize, SMEM_DYN);
    cudaFuncSetAttribute(gemm_mma_kernel<1>,
                         cudaFuncAttributeMaxDynamicSharedMemorySize, SMEM_DYN);

    fill_synwin_kernel<<<1, 1024>>>();
    fill_binv_kernel<<<2048, 256>>>();
    fill_bfwd_kernel<<<2048, 256>>>();
    convert_x_kernel<<<dim3(8, NB), 256>>>(x);

    gemm_mma_kernel<0><<<dim3(8, 162), 256, SMEM_DYN>>>(nullptr);

    pad_frames_kernel<<<(M2 + 255) / 256, 256>>>();
    fold_kernel<<<dim3((OUTJ + 255) / 256, NB), 256>>>();

    gemm_mma_kernel<1><<<dim3(8, 138), 256, SMEM_DYN>>>(out);
}